// round 3
// baseline (speedup 1.0000x reference)
#include <cuda_runtime.h>
#include <cstdint>
#include <cstddef>

// Problem dims (fixed)
#define BB   32
#define TT   4096
#define DIN  256
#define HH   256
#define G4   1024   // 4*H

// ---------------- scratch (static device arrays; no allocation) ----------------
__device__ float g_xg[(size_t)BB * TT * G4];   // 512 MB : x @ Wx + b
__device__ float g_hseq[(size_t)BB * TT * HH]; // 128 MB : h_t for all t

// ---------------- small PTX helpers ----------------
__device__ __forceinline__ unsigned long long ffma2(unsigned long long a,
                                                    unsigned long long b,
                                                    unsigned long long c) {
    unsigned long long d;
    asm("fma.rn.f32x2 %0, %1, %2, %3;" : "=l"(d) : "l"(a), "l"(b), "l"(c));
    return d;
}
__device__ __forceinline__ unsigned long long pk2(float lo, float hi) {
    unsigned long long r;
    asm("mov.b64 %0, {%1,%2};" : "=l"(r) : "f"(lo), "f"(hi));
    return r;
}
__device__ __forceinline__ float2 unpk2(unsigned long long v) {
    float lo, hi;
    asm("mov.b64 {%0,%1}, %2;" : "=f"(lo), "=f"(hi) : "l"(v));
    return make_float2(lo, hi);
}
__device__ __forceinline__ uint32_t s2u(const void* p) {
    return (uint32_t)__cvta_generic_to_shared(p);
}
__device__ __forceinline__ uint32_t mapa_u32(uint32_t addr, uint32_t rank) {
    uint32_t r;
    asm("mapa.shared::cluster.u32 %0, %1, %2;" : "=r"(r) : "r"(addr), "r"(rank));
    return r;
}
__device__ __forceinline__ void st_cluster_f32(uint32_t addr, float v) {
    asm volatile("st.shared::cluster.f32 [%0], %1;" :: "r"(addr), "f"(v) : "memory");
}
__device__ __forceinline__ void arrive_cluster(uint32_t bar) {
    asm volatile("mbarrier.arrive.release.cluster.shared::cluster.b64 _, [%0];"
                 :: "r"(bar) : "memory");
}
__device__ __forceinline__ void bar_init(uint32_t bar, uint32_t cnt) {
    asm volatile("mbarrier.init.shared.b64 [%0], %1;" :: "r"(bar), "r"(cnt) : "memory");
}
__device__ __forceinline__ void wait_bar(uint32_t bar, uint32_t parity) {
    asm volatile(
        "{\n\t"
        ".reg .pred P;\n\t"
        "WL%=:\n\t"
        "mbarrier.try_wait.parity.acquire.cluster.shared::cta.b64 P, [%0], %1, 0x989680;\n\t"
        "@P bra WD%=;\n\t"
        "bra WL%=;\n\t"
        "WD%=:\n\t"
        "}"
        :: "r"(bar), "r"(parity) : "memory");
}

// ---------------- generic fp32 GEMM: C[M,N] = A[M,K] @ B[K,N] + bias[N] -------
// BM=128, BN=128, BK=8, 256 threads, 8x8 microtile (split-tile, conflict-free LDS.128)
__global__ void __launch_bounds__(256) sgemm_bias_128(
    const float* __restrict__ A, const float* __restrict__ B,
    const float* __restrict__ bias, float* __restrict__ C,
    int M, int N, int K)
{
    __shared__ __align__(16) float As[8][128];
    __shared__ __align__(16) float Bs[8][128];

    const int tid = threadIdx.x;
    const int bm  = blockIdx.y;
    const int bn  = blockIdx.x;
    const int tx  = tid & 15;
    const int ty  = tid >> 4;

    const int arow = tid >> 1;
    const int ak   = (tid & 1) * 4;
    const int brow = tid >> 5;
    const int bcol = (tid & 31) * 4;

    const float* Aptr = A + (size_t)(bm * 128 + arow) * K + ak;
    const float* Bptr = B + (size_t)brow * N + bn * 128 + bcol;

    float acc[8][8];
#pragma unroll
    for (int i = 0; i < 8; i++)
#pragma unroll
        for (int j = 0; j < 8; j++) acc[i][j] = 0.f;

    for (int k0 = 0; k0 < K; k0 += 8) {
        const float4 va = *(const float4*)(Aptr + k0);
        const float4 vb = *(const float4*)(Bptr + (size_t)k0 * N);
        __syncthreads();
        As[ak + 0][arow] = va.x;
        As[ak + 1][arow] = va.y;
        As[ak + 2][arow] = va.z;
        As[ak + 3][arow] = va.w;
        *(float4*)&Bs[brow][bcol] = vb;
        __syncthreads();

#pragma unroll
        for (int k = 0; k < 8; k++) {
            float a0[4], a1[4], b0v[4], b1v[4];
            *(float4*)a0  = *(const float4*)&As[k][ty * 4];
            *(float4*)a1  = *(const float4*)&As[k][64 + ty * 4];
            *(float4*)b0v = *(const float4*)&Bs[k][tx * 4];
            *(float4*)b1v = *(const float4*)&Bs[k][64 + tx * 4];
#pragma unroll
            for (int i = 0; i < 4; i++) {
#pragma unroll
                for (int j = 0; j < 4; j++) {
                    acc[i][j]         = fmaf(a0[i], b0v[j], acc[i][j]);
                    acc[i][j + 4]     = fmaf(a0[i], b1v[j], acc[i][j + 4]);
                    acc[i + 4][j]     = fmaf(a1[i], b0v[j], acc[i + 4][j]);
                    acc[i + 4][j + 4] = fmaf(a1[i], b1v[j], acc[i + 4][j + 4]);
                }
            }
        }
    }

    float bvals[8];
#pragma unroll
    for (int j = 0; j < 4; j++) {
        bvals[j]     = bias[bn * 128 + tx * 4 + j];
        bvals[j + 4] = bias[bn * 128 + 64 + tx * 4 + j];
    }

#pragma unroll
    for (int i = 0; i < 8; i++) {
        const int row = bm * 128 + ((i < 4) ? (ty * 4 + i) : (64 + ty * 4 + (i - 4)));
        float4 o0, o1;
        o0.x = acc[i][0] + bvals[0]; o0.y = acc[i][1] + bvals[1];
        o0.z = acc[i][2] + bvals[2]; o0.w = acc[i][3] + bvals[3];
        o1.x = acc[i][4] + bvals[4]; o1.y = acc[i][5] + bvals[5];
        o1.z = acc[i][6] + bvals[6]; o1.w = acc[i][7] + bvals[7];
        *(float4*)&C[(size_t)row * N + bn * 128 + tx * 4]      = o0;
        *(float4*)&C[(size_t)row * N + bn * 128 + 64 + tx * 4] = o1;
    }
}

// ---------------- recurrence kernel (8-CTA clusters, DSMEM exchange, f32x2) ----
// 128 CTAs = 16 clusters x 8. Cluster = one batch pair (b0,b1).
// CTA rank j owns gate-columns {gate*256 + j*32 + l : gate<4, l<32} (128 cols) for 2 batches.
// 256 threads = 128 cols x 2 K-halves. Wh slice pre-packed along K into 64 b64 regs
// (f32x2 lanes). Per step: 128 FFMA2/thread -> 512-cyc issue floor per SM.
// h exchange: 64 activation threads store h directly into all 8 peers' SMEM
// (st.shared::cluster) + per-thread release-arrive on peers' 512-count mbarrier;
// everyone acquires via try_wait.parity. Double-buffered by step parity.
__global__ void __launch_bounds__(256, 1) __cluster_dims__(8, 1, 1)
lstm_rec(const float* __restrict__ Wh)
{
    const int cta  = blockIdx.x;
    const int grp  = cta >> 3;        // batch pair
    const int b0   = grp * 2, b1 = b0 + 1;
    const int tid  = threadIdx.x;
    const int q    = tid & 127;       // col within CTA
    const int kh   = tid >> 7;        // K-half (uniform per warp)
    const int gate = q >> 5;
    const int l    = q & 31;
    uint32_t rank;
    asm("mov.u32 %0, %%cluster_ctarank;" : "=r"(rank));
    const int colg = gate * 256 + (int)rank * 32 + l;  // column in [0,1024)

    __shared__ __align__(16) float hs[2][2][256];      // parity x batch x h
    __shared__ float red0[128], red1[128];
    __shared__ float gsm0[128], gsm1[128];
    __shared__ float csm[2][32];
    __shared__ __align__(8) unsigned long long mbar[2];

    // ---- persistent packed weights: w2[jj] = (Wh[k0+2jj][colg], Wh[k0+2jj+1][colg]) ----
    unsigned long long w2[64];
    {
        const float* wp = Wh + (size_t)(kh * 128) * G4 + colg;
#pragma unroll
        for (int jj = 0; jj < 64; jj++) {
            float lo = __ldg(&wp[(size_t)(2 * jj) * G4]);
            float hi = __ldg(&wp[(size_t)(2 * jj + 1) * G4]);
            w2[jj] = pk2(lo, hi);
        }
    }

    // ---- init state ----
    ((float4*)hs)[tid] = make_float4(0.f, 0.f, 0.f, 0.f);   // 1024 floats / 4 = 256
    if (tid < 64) csm[tid >> 5][tid & 31] = 0.f;
    const uint32_t hsu   = s2u(hs);
    const uint32_t baru0 = s2u(&mbar[0]);
    const uint32_t baru1 = s2u(&mbar[1]);
    if (tid == 0) {
        bar_init(baru0, 512);   // 8 CTAs x 64 activation threads
        bar_init(baru1, 512);
    }
    __syncthreads();
    asm volatile("barrier.cluster.arrive.aligned;" ::: "memory");
    asm volatile("barrier.cluster.wait.aligned;" ::: "memory");

    int ph0 = 0, ph1 = 0;

    for (int t = 0; t < TT; t++) {
        const int p = t & 1;

        // xg for this step (consumed by kh==0 after the FMA loop; issue early)
        float xv0 = 0.f, xv1 = 0.f;
        if (kh == 0) {
            xv0 = __ldg(&g_xg[((size_t)(b0 * TT + t)) * G4 + colg]);
            xv1 = __ldg(&g_xg[((size_t)(b1 * TT + t)) * G4 + colg]);
        }

        // partial dot over this thread's K-half, 2 batches, f32x2 packed along K
        const ulonglong2* h0v = (const ulonglong2*)&hs[p][0][kh * 128];
        const ulonglong2* h1v = (const ulonglong2*)&hs[p][1][kh * 128];
        unsigned long long a00 = 0ull, a01 = 0ull, a10 = 0ull, a11 = 0ull;
#pragma unroll
        for (int jj = 0; jj < 32; jj++) {
            const ulonglong2 h0 = h0v[jj];
            const ulonglong2 h1 = h1v[jj];
            a00 = ffma2(w2[2 * jj],     h0.x, a00);
            a01 = ffma2(w2[2 * jj + 1], h0.y, a01);
            a10 = ffma2(w2[2 * jj],     h1.x, a10);
            a11 = ffma2(w2[2 * jj + 1], h1.y, a11);
        }
        float s0, s1;
        {
            const float2 u0 = unpk2(a00), u1 = unpk2(a01);
            const float2 v0 = unpk2(a10), v1 = unpk2(a11);
            s0 = (u0.x + u0.y) + (u1.x + u1.y);
            s1 = (v0.x + v0.y) + (v1.x + v1.y);
        }

        if (kh == 1) { red0[q] = s0; red1[q] = s1; }
        __syncthreads();
        if (kh == 0) {
            gsm0[q] = s0 + red0[q] + xv0;   // bias folded into xg
            gsm1[q] = s1 + red1[q] + xv1;
        }
        __syncthreads();

        const int p2 = p ^ 1;
        const uint32_t lbar = p2 ? baru1 : baru0;

        // activation + state update + DSMEM broadcast: 64 threads = 2 batches x 32 h
        if (tid < 64) {
            const int bb = tid >> 5, ll = tid & 31;
            const float* gp = bb ? gsm1 : gsm0;
            const float gi = gp[ll];
            const float gf = gp[32 + ll];
            const float gg = gp[64 + ll];
            const float go = gp[96 + ll];
            const float cprev = csm[bb][ll];
            const float si = 1.f / (1.f + __expf(-gi));
            const float sf = 1.f / (1.f + __expf(-gf));
            const float so = 1.f / (1.f + __expf(-go));
            const float tg = 2.f / (1.f + __expf(-2.f * gg)) - 1.f;
            const float cn = sf * cprev + si * tg;
            const float tc = 2.f / (1.f + __expf(-2.f * cn)) - 1.f;
            const float hn = so * tc;
            csm[bb][ll] = cn;

            const int bg   = bb ? b1 : b0;
            const int hidx = (int)rank * 32 + ll;
            g_hseq[((size_t)(bg * TT + t)) * HH + hidx] = hn;

            if (t + 1 < TT) {
                // broadcast h to all 8 cluster CTAs' hs[p2][bb][hidx]
                const uint32_t loff = hsu + (uint32_t)(((p2 * 2 + bb) * 256 + hidx) * 4);
#pragma unroll
                for (int r = 0; r < 8; r++)
                    st_cluster_f32(mapa_u32(loff, (uint32_t)r), hn);
#pragma unroll
                for (int r = 0; r < 8; r++)
                    arrive_cluster(mapa_u32(lbar, (uint32_t)r));
            }
        }

        if (t + 1 < TT) {
            const int phv = p2 ? ph1 : ph0;
            wait_bar(lbar, (uint32_t)phv);
            if (p2) ph1 ^= 1; else ph0 ^= 1;
        }
    }

    // lifetime: no CTA may exit while peers could still store into its SMEM
    asm volatile("barrier.cluster.arrive.aligned;" ::: "memory");
    asm volatile("barrier.cluster.wait.aligned;" ::: "memory");
}

// ---------------- launch ----------------
extern "C" void kernel_launch(void* const* d_in, const int* in_sizes, int n_in,
                              void* d_out, int out_size)
{
    const float* x  = (const float*)d_in[0];   // [B,T,DIN]
    const float* Wx = (const float*)d_in[1];   // [DIN,4H]
    const float* Wh = (const float*)d_in[2];   // [H,4H]
    const float* b  = (const float*)d_in[3];   // [4H]
    const float* Wo = (const float*)d_in[4];   // [H,DOUT]
    const float* bo = (const float*)d_in[5];   // [DOUT]
    float* out = (float*)d_out;                // [B,T,DOUT]

    float *xg_ptr = nullptr, *hseq_ptr = nullptr;
    cudaGetSymbolAddress((void**)&xg_ptr, g_xg);
    cudaGetSymbolAddress((void**)&hseq_ptr, g_hseq);

    // 1) xg = x @ Wx + b : [131072,256] @ [256,1024]
    {
        dim3 grid(G4 / 128, (BB * TT) / 128);   // (8, 1024)
        sgemm_bias_128<<<grid, 256>>>(x, Wx, b, xg_ptr, BB * TT, G4, DIN);
    }

    // 2) recurrence over 4096 steps (16 clusters x 8 CTAs)
    lstm_rec<<<128, 256>>>(Wh);

    // 3) out = hseq @ Wo + bo : [131072,256] @ [256,256]
    {
        dim3 grid(256 / 128, (BB * TT) / 128);  // (2, 1024)
        sgemm_bias_128<<<grid, 256>>>(hseq_ptr, Wo, bo, out, BB * TT, 256, HH);
    }
}

// round 4
// speedup vs baseline: 2.5259x; 2.5259x over previous
#include <cuda_runtime.h>
#include <cstdint>
#include <cstddef>

// Problem dims (fixed)
#define BB   32
#define TT   4096
#define DIN  256
#define HH   256
#define G4   1024   // 4*H

// ---------------- scratch (static device arrays; no allocation) ----------------
__device__ float    g_xg[(size_t)BB * TT * G4];   // 512 MB : x @ Wx + b
__device__ float    g_hseq[(size_t)BB * TT * HH]; // 128 MB : h_t for all t
__device__ float    g_hbuf[2][BB * HH];           // parity double-buffered h exchange
__device__ unsigned g_flag[128];                  // grp*8+rank, monotone step counters

__global__ void init_kernel() {
    if (threadIdx.x < 128) g_flag[threadIdx.x] = 0u;
}

// ---------------- PTX helpers ----------------
__device__ __forceinline__ unsigned long long ffma2(unsigned long long a,
                                                    unsigned long long b,
                                                    unsigned long long c) {
    unsigned long long d;
    asm("fma.rn.f32x2 %0, %1, %2, %3;" : "=l"(d) : "l"(a), "l"(b), "l"(c));
    return d;
}
__device__ __forceinline__ unsigned long long addx2(unsigned long long a,
                                                    unsigned long long b) {
    unsigned long long d;
    asm("add.rn.f32x2 %0, %1, %2;" : "=l"(d) : "l"(a), "l"(b));
    return d;
}
__device__ __forceinline__ unsigned long long pk2(float lo, float hi) {
    unsigned long long r;
    asm("mov.b64 %0, {%1,%2};" : "=l"(r) : "f"(lo), "f"(hi));
    return r;
}
__device__ __forceinline__ float2 unpk2(unsigned long long v) {
    float lo, hi;
    asm("mov.b64 {%0,%1}, %2;" : "=f"(lo), "=f"(hi) : "l"(v));
    return make_float2(lo, hi);
}
__device__ __forceinline__ void st_flag(unsigned* p, unsigned v) {
    asm volatile("st.global.cg.u32 [%0], %1;" :: "l"(p), "r"(v) : "memory");
}
__device__ __forceinline__ unsigned ld_acq(const unsigned* p) {
    unsigned v;
    asm volatile("ld.acquire.gpu.global.u32 %0, [%1];" : "=r"(v) : "l"(p) : "memory");
    return v;
}

// ---------------- fp32 GEMM (f32x2 inner loop): C = A@B + bias ----------------
// BM=128, BN=128, BK=8, 256 threads, 8x8 microtile; column-pairs packed into
// fma.rn.f32x2 -> 32 FFMA2/k instead of 64 FFMA/k.
__global__ void __launch_bounds__(256) sgemm_bias_128(
    const float* __restrict__ A, const float* __restrict__ B,
    const float* __restrict__ bias, float* __restrict__ C,
    int M, int N, int K)
{
    __shared__ __align__(16) float As[8][128];
    __shared__ __align__(16) float Bs[8][128];

    const int tid = threadIdx.x;
    const int bm  = blockIdx.y;
    const int bn  = blockIdx.x;
    const int tx  = tid & 15;
    const int ty  = tid >> 4;

    const int arow = tid >> 1;
    const int ak   = (tid & 1) * 4;
    const int brow = tid >> 5;
    const int bcol = (tid & 31) * 4;

    const float* Aptr = A + (size_t)(bm * 128 + arow) * K + ak;
    const float* Bptr = B + (size_t)brow * N + bn * 128 + bcol;

    unsigned long long acc2[8][4];   // 8 rows x 4 col-pairs
#pragma unroll
    for (int i = 0; i < 8; i++)
#pragma unroll
        for (int jp = 0; jp < 4; jp++) acc2[i][jp] = 0ull;

    for (int k0 = 0; k0 < K; k0 += 8) {
        const float4 va = *(const float4*)(Aptr + k0);
        const float4 vb = *(const float4*)(Bptr + (size_t)k0 * N);
        __syncthreads();
        As[ak + 0][arow] = va.x;
        As[ak + 1][arow] = va.y;
        As[ak + 2][arow] = va.z;
        As[ak + 3][arow] = va.w;
        *(float4*)&Bs[brow][bcol] = vb;
        __syncthreads();

#pragma unroll
        for (int k = 0; k < 8; k++) {
            float a0[4], a1[4];
            *(float4*)a0 = *(const float4*)&As[k][ty * 4];
            *(float4*)a1 = *(const float4*)&As[k][64 + ty * 4];
            const ulonglong2 bp0 = *(const ulonglong2*)&Bs[k][tx * 4];
            const ulonglong2 bp1 = *(const ulonglong2*)&Bs[k][64 + tx * 4];
#pragma unroll
            for (int i = 0; i < 4; i++) {
                const unsigned long long ad0 = pk2(a0[i], a0[i]);
                acc2[i][0] = ffma2(ad0, bp0.x, acc2[i][0]);
                acc2[i][1] = ffma2(ad0, bp0.y, acc2[i][1]);
                acc2[i][2] = ffma2(ad0, bp1.x, acc2[i][2]);
                acc2[i][3] = ffma2(ad0, bp1.y, acc2[i][3]);
                const unsigned long long ad1 = pk2(a1[i], a1[i]);
                acc2[i + 4][0] = ffma2(ad1, bp0.x, acc2[i + 4][0]);
                acc2[i + 4][1] = ffma2(ad1, bp0.y, acc2[i + 4][1]);
                acc2[i + 4][2] = ffma2(ad1, bp1.x, acc2[i + 4][2]);
                acc2[i + 4][3] = ffma2(ad1, bp1.y, acc2[i + 4][3]);
            }
        }
    }

    const float* bptr = bias + bn * 128;
    const ulonglong2 bv0 = *(const ulonglong2*)&bptr[tx * 4];
    const ulonglong2 bv1 = *(const ulonglong2*)&bptr[64 + tx * 4];

#pragma unroll
    for (int i = 0; i < 8; i++) {
        const int row = bm * 128 + ((i < 4) ? (ty * 4 + i) : (64 + ty * 4 + (i - 4)));
        ulonglong2 o0, o1;
        o0.x = addx2(acc2[i][0], bv0.x);
        o0.y = addx2(acc2[i][1], bv0.y);
        o1.x = addx2(acc2[i][2], bv1.x);
        o1.y = addx2(acc2[i][3], bv1.y);
        *(ulonglong2*)&C[(size_t)row * N + bn * 128 + tx * 4]      = o0;
        *(ulonglong2*)&C[(size_t)row * N + bn * 128 + 64 + tx * 4] = o1;
    }
}

// ---------------- recurrence (L2 flag sync, f32x2, intra-warp K-reduce) -------
// 128 CTAs = 16 groups x 8 ranks. Group = batch pair (b0,b1). Rank j owns
// gate-columns {gate*256 + j*32 + l}. 256 threads = 8 warps; within a warp,
// lanes 0-15 are K-half 0, lanes 16-31 are K-half 1, of the same 16 columns
// (cross-half reduce = one shfl.bfly 16). Wh slice packed along K into 64 b64
// regs (f32x2) -> 512-cyc FMA issue floor/step. Exchange: writers st.cg h into
// parity buffer + monotone per-rank flag (one 32B sector per group); readers
// ld.acquire-poll 8 flags coalesced, then ld.cg reload. All 128 CTAs co-resident.
__global__ void __launch_bounds__(256, 1) lstm_rec(const float* __restrict__ Wh)
{
    const int cta  = blockIdx.x;
    const int grp  = cta >> 3;
    const int j    = cta & 7;
    const int b0   = grp * 2, b1 = b0 + 1;
    const int tid  = threadIdx.x;
    const int w    = tid >> 5;
    const int lane = tid & 31;
    const int q    = w * 16 + (lane & 15);   // col within CTA, 0..127
    const int kh   = lane >> 4;              // K-half
    const int gate = q >> 5;
    const int l    = q & 31;
    const int colg = gate * 256 + j * 32 + l;

    __shared__ __align__(16) float hs0[256];
    __shared__ __align__(16) float hs1[256];
    __shared__ float gsm0[128], gsm1[128];
    __shared__ float csm[2][32];

    // persistent packed weights: w2[jj] = (Wh[k0+2jj][colg], Wh[k0+2jj+1][colg])
    unsigned long long w2[64];
    {
        const float* wp = Wh + (size_t)(kh * 128) * G4 + colg;
#pragma unroll
        for (int jj = 0; jj < 64; jj++) {
            const float lo = __ldg(&wp[(size_t)(2 * jj) * G4]);
            const float hi = __ldg(&wp[(size_t)(2 * jj + 1) * G4]);
            w2[jj] = pk2(lo, hi);
        }
    }

    hs0[tid] = 0.f;
    hs1[tid] = 0.f;
    if (tid < 64) csm[tid >> 5][tid & 31] = 0.f;
    __syncthreads();

    // preload xg for t=0 (kh==0 lanes are the gate writers)
    float xv0 = 0.f, xv1 = 0.f;
    if (kh == 0) {
        xv0 = __ldg(&g_xg[((size_t)(b0 * TT)) * G4 + colg]);
        xv1 = __ldg(&g_xg[((size_t)(b1 * TT)) * G4 + colg]);
    }

    for (int t = 0; t < TT; t++) {
        // partial dot over this lane's K-half, 2 batches, f32x2 packed along K
        const ulonglong2* h0v = (const ulonglong2*)&hs0[kh * 128];
        const ulonglong2* h1v = (const ulonglong2*)&hs1[kh * 128];
        unsigned long long a00 = 0ull, a01 = 0ull, a10 = 0ull, a11 = 0ull;
#pragma unroll
        for (int jj = 0; jj < 32; jj++) {
            const ulonglong2 h0 = h0v[jj];
            const ulonglong2 h1 = h1v[jj];
            a00 = ffma2(w2[2 * jj],     h0.x, a00);
            a01 = ffma2(w2[2 * jj + 1], h0.y, a01);
            a10 = ffma2(w2[2 * jj],     h1.x, a10);
            a11 = ffma2(w2[2 * jj + 1], h1.y, a11);
        }
        float s0, s1;
        {
            const float2 u0 = unpk2(a00), u1 = unpk2(a01);
            const float2 v0 = unpk2(a10), v1 = unpk2(a11);
            s0 = (u0.x + u0.y) + (u1.x + u1.y);
            s1 = (v0.x + v0.y) + (v1.x + v1.y);
        }
        // cross-half reduce inside the warp
        s0 += __shfl_xor_sync(0xffffffffu, s0, 16);
        s1 += __shfl_xor_sync(0xffffffffu, s1, 16);
        if (kh == 0) {
            gsm0[q] = s0 + xv0;   // bias folded into xg
            gsm1[q] = s1 + xv1;
        }
        __syncthreads();

        // activation + state update: 64 threads = 2 batches x 32 h-indices
        float hn = 0.f;
        int bg = 0, hidx = 0;
        if (tid < 64) {
            const int bb = tid >> 5, ll = tid & 31;
            const float* gp = bb ? gsm1 : gsm0;
            const float gi = gp[ll];
            const float gf = gp[32 + ll];
            const float gg = gp[64 + ll];
            const float go = gp[96 + ll];
            const float cprev = csm[bb][ll];
            const float si = 1.f / (1.f + __expf(-gi));
            const float sf = 1.f / (1.f + __expf(-gf));
            const float so = 1.f / (1.f + __expf(-go));
            const float tg = 2.f / (1.f + __expf(-2.f * gg)) - 1.f;
            const float cn = sf * cprev + si * tg;
            const float tc = 2.f / (1.f + __expf(-2.f * cn)) - 1.f;
            hn = so * tc;
            csm[bb][ll] = cn;
            bg   = bb ? b1 : b0;
            hidx = j * 32 + ll;
            if (t + 1 < TT)
                __stcg(&g_hbuf[(t + 1) & 1][bg * HH + hidx], hn);
        }
        __syncthreads();

        if (t + 1 < TT) {
            // publish flag (monotone; one word per rank, 8 words = 1 sector/group)
            if (tid == 0) {
                __threadfence();
                st_flag(&g_flag[grp * 8 + j], (unsigned)(t + 1));
            }
            // off-critical-path work while the flag propagates:
            if (tid < 64)
                g_hseq[((size_t)(bg * TT + t)) * HH + hidx] = hn;
            float nx0 = 0.f, nx1 = 0.f;
            if (kh == 0) {   // prefetch next xg (overlaps the wait)
                nx0 = __ldg(&g_xg[((size_t)(b0 * TT + (t + 1))) * G4 + colg]);
                nx1 = __ldg(&g_xg[((size_t)(b1 * TT + (t + 1))) * G4 + colg]);
            }
            // wait for all 8 ranks of this group
            if (tid < 8) {
                const unsigned want = (unsigned)(t + 1);
                unsigned v;
                do { v = ld_acq(&g_flag[grp * 8 + tid]); } while (v < want);
            }
            __syncthreads();
            hs0[tid] = __ldcg(&g_hbuf[(t + 1) & 1][b0 * HH + tid]);
            hs1[tid] = __ldcg(&g_hbuf[(t + 1) & 1][b1 * HH + tid]);
            xv0 = nx0; xv1 = nx1;
            __syncthreads();
        } else {
            if (tid < 64)
                g_hseq[((size_t)(bg * TT + t)) * HH + hidx] = hn;
        }
    }
}

// ---------------- launch ----------------
extern "C" void kernel_launch(void* const* d_in, const int* in_sizes, int n_in,
                              void* d_out, int out_size)
{
    const float* x  = (const float*)d_in[0];   // [B,T,DIN]
    const float* Wx = (const float*)d_in[1];   // [DIN,4H]
    const float* Wh = (const float*)d_in[2];   // [H,4H]
    const float* b  = (const float*)d_in[3];   // [4H]
    const float* Wo = (const float*)d_in[4];   // [H,DOUT]
    const float* bo = (const float*)d_in[5];   // [DOUT]
    float* out = (float*)d_out;                // [B,T,DOUT]

    float *xg_ptr = nullptr, *hseq_ptr = nullptr;
    cudaGetSymbolAddress((void**)&xg_ptr, g_xg);
    cudaGetSymbolAddress((void**)&hseq_ptr, g_hseq);

    // reset flags (graph replays reuse device state)
    init_kernel<<<1, 128>>>();

    // 1) xg = x @ Wx + b : [131072,256] @ [256,1024]
    {
        dim3 grid(G4 / 128, (BB * TT) / 128);   // (8, 1024)
        sgemm_bias_128<<<grid, 256>>>(x, Wx, b, xg_ptr, BB * TT, G4, DIN);
    }

    // 2) recurrence over 4096 steps (16 groups x 8 CTAs, all co-resident)
    lstm_rec<<<128, 256>>>(Wh);

    // 3) out = hseq @ Wo + bo : [131072,256] @ [256,256]
    {
        dim3 grid(256 / 128, (BB * TT) / 128);  // (2, 1024)
        sgemm_bias_128<<<grid, 256>>>(hseq_ptr, Wo, bo, out, BB * TT, 256, HH);
    }
}

// round 7
// speedup vs baseline: 3.1919x; 1.2637x over previous
#include <cuda_runtime.h>
#include <cstdint>
#include <cstddef>

// Problem dims (fixed)
#define BB   32
#define TT   4096
#define DIN  256
#define HH   256
#define G4   1024   // 4*H

// ---------------- scratch (static device arrays; no allocation) ----------------
__device__ float g_xg[(size_t)BB * TT * G4];   // 512 MB : x @ Wx + b
__device__ float g_hseq[(size_t)BB * TT * HH]; // 128 MB : h_t for all t
// tagged exchange: [slot][group][hidx][batch] = {h, tag} in one 8B word,
// accessed ONLY with relaxed atomics (spec-guaranteed single-copy atomic).
__device__ unsigned long long g_hx[2][16][256][2];

__global__ void init_kernel() {   // zero tags for graph replays
    const int i = blockIdx.x * 256 + threadIdx.x;   // 16384 u64s
    ((unsigned long long*)g_hx)[i] = 0ull;
}

// ---------------- PTX helpers ----------------
__device__ __forceinline__ unsigned long long ffma2(unsigned long long a,
                                                    unsigned long long b,
                                                    unsigned long long c) {
    unsigned long long d;
    asm("fma.rn.f32x2 %0, %1, %2, %3;" : "=l"(d) : "l"(a), "l"(b), "l"(c));
    return d;
}
__device__ __forceinline__ unsigned long long addx2(unsigned long long a,
                                                    unsigned long long b) {
    unsigned long long d;
    asm("add.rn.f32x2 %0, %1, %2;" : "=l"(d) : "l"(a), "l"(b));
    return d;
}
__device__ __forceinline__ unsigned long long pk2(float lo, float hi) {
    unsigned long long r;
    asm("mov.b64 %0, {%1,%2};" : "=l"(r) : "f"(lo), "f"(hi));
    return r;
}
__device__ __forceinline__ float2 unpk2(unsigned long long v) {
    float lo, hi;
    asm("mov.b64 {%0,%1}, %2;" : "=f"(lo), "=f"(hi) : "l"(v));
    return make_float2(lo, hi);
}
// relaxed 8B atomics: tear-free by the PTX memory model, no fence cost
__device__ __forceinline__ void st_rlx64(unsigned long long* p, unsigned long long v) {
    asm volatile("st.relaxed.gpu.global.u64 [%0], %1;" :: "l"(p), "l"(v) : "memory");
}
__device__ __forceinline__ unsigned long long ld_rlx64(const unsigned long long* p) {
    unsigned long long v;
    asm volatile("ld.relaxed.gpu.global.u64 %0, [%1];" : "=l"(v) : "l"(p) : "memory");
    return v;
}

// ---------------- fp32 GEMM (f32x2 inner loop): C = A@B + bias ----------------
__global__ void __launch_bounds__(256) sgemm_bias_128(
    const float* __restrict__ A, const float* __restrict__ B,
    const float* __restrict__ bias, float* __restrict__ C,
    int M, int N, int K)
{
    __shared__ __align__(16) float As[8][128];
    __shared__ __align__(16) float Bs[8][128];

    const int tid = threadIdx.x;
    const int bm  = blockIdx.y;
    const int bn  = blockIdx.x;
    const int tx  = tid & 15;
    const int ty  = tid >> 4;

    const int arow = tid >> 1;
    const int ak   = (tid & 1) * 4;
    const int brow = tid >> 5;
    const int bcol = (tid & 31) * 4;

    const float* Aptr = A + (size_t)(bm * 128 + arow) * K + ak;
    const float* Bptr = B + (size_t)brow * N + bn * 128 + bcol;

    unsigned long long acc2[8][4];
#pragma unroll
    for (int i = 0; i < 8; i++)
#pragma unroll
        for (int jp = 0; jp < 4; jp++) acc2[i][jp] = 0ull;

    for (int k0 = 0; k0 < K; k0 += 8) {
        const float4 va = *(const float4*)(Aptr + k0);
        const float4 vb = *(const float4*)(Bptr + (size_t)k0 * N);
        __syncthreads();
        As[ak + 0][arow] = va.x;
        As[ak + 1][arow] = va.y;
        As[ak + 2][arow] = va.z;
        As[ak + 3][arow] = va.w;
        *(float4*)&Bs[brow][bcol] = vb;
        __syncthreads();

#pragma unroll
        for (int k = 0; k < 8; k++) {
            float a0[4], a1[4];
            *(float4*)a0 = *(const float4*)&As[k][ty * 4];
            *(float4*)a1 = *(const float4*)&As[k][64 + ty * 4];
            const ulonglong2 bp0 = *(const ulonglong2*)&Bs[k][tx * 4];
            const ulonglong2 bp1 = *(const ulonglong2*)&Bs[k][64 + tx * 4];
#pragma unroll
            for (int i = 0; i < 4; i++) {
                const unsigned long long ad0 = pk2(a0[i], a0[i]);
                acc2[i][0] = ffma2(ad0, bp0.x, acc2[i][0]);
                acc2[i][1] = ffma2(ad0, bp0.y, acc2[i][1]);
                acc2[i][2] = ffma2(ad0, bp1.x, acc2[i][2]);
                acc2[i][3] = ffma2(ad0, bp1.y, acc2[i][3]);
                const unsigned long long ad1 = pk2(a1[i], a1[i]);
                acc2[i + 4][0] = ffma2(ad1, bp0.x, acc2[i + 4][0]);
                acc2[i + 4][1] = ffma2(ad1, bp0.y, acc2[i + 4][1]);
                acc2[i + 4][2] = ffma2(ad1, bp1.x, acc2[i + 4][2]);
                acc2[i + 4][3] = ffma2(ad1, bp1.y, acc2[i + 4][3]);
            }
        }
    }

    const float* bptr = bias + bn * 128;
    const ulonglong2 bv0 = *(const ulonglong2*)&bptr[tx * 4];
    const ulonglong2 bv1 = *(const ulonglong2*)&bptr[64 + tx * 4];

#pragma unroll
    for (int i = 0; i < 8; i++) {
        const int row = bm * 128 + ((i < 4) ? (ty * 4 + i) : (64 + ty * 4 + (i - 4)));
        ulonglong2 o0, o1;
        o0.x = addx2(acc2[i][0], bv0.x);
        o0.y = addx2(acc2[i][1], bv0.y);
        o1.x = addx2(acc2[i][2], bv1.x);
        o1.y = addx2(acc2[i][3], bv1.y);
        *(ulonglong2*)&C[(size_t)row * N + bn * 128 + tx * 4]      = o0;
        *(ulonglong2*)&C[(size_t)row * N + bn * 128 + 64 + tx * 4] = o1;
    }
}

// ---------------- recurrence: R4 skeleton + relaxed-atomic tagged exchange -----
// 128 CTAs = 16 groups (batch pairs) x 8 ranks. Rank j owns gate-columns
// {gate*256 + j*32 + l}. 256 threads = 8 warps; lanes 0-15 = K-half 0,
// lanes 16-31 = K-half 1 of the same 16 columns (cross-half reduce = shfl 16).
// Wh packed along K into 64 b64 regs (f32x2) -> 512-cyc FFMA2 floor/step.
// Activation: EXACT R4 structure (tid<64, 2 batches x 32 h, csm in SMEM).
// Exchange: each activation thread stores its {h, tag} as ONE 8B relaxed-atomic
// word; every thread polls its own two words (both batches of hidx=tid) with
// relaxed-atomic loads until both tags >= t+1. Tag travels with data => no
// fences, no flags, no separate reload. 2 barriers/step; warps 2-7 poll while
// warps 0-1 run activations. Parity double-buffered; the all-ranks poll each
// step bounds skew to 1 so slot reuse is safe; monotone tags; init zeroes tags.
__global__ void __launch_bounds__(256, 1) lstm_rec(const float* __restrict__ Wh)
{
    const int cta  = blockIdx.x;
    const int grp  = cta >> 3;
    const int j    = cta & 7;
    const int b0   = grp * 2, b1 = b0 + 1;
    const int tid  = threadIdx.x;
    const int w    = tid >> 5;
    const int lane = tid & 31;
    const int q    = w * 16 + (lane & 15);   // col within CTA, 0..127
    const int kh   = lane >> 4;              // K-half
    const int gate = q >> 5;
    const int l    = q & 31;
    const int colg = gate * 256 + j * 32 + l;

    __shared__ __align__(16) float hs0[256];
    __shared__ __align__(16) float hs1[256];
    __shared__ float gsm0[128], gsm1[128];
    __shared__ float csm[2][32];

    // persistent packed weights: w2[jj] = (Wh[k0+2jj][colg], Wh[k0+2jj+1][colg])
    unsigned long long w2[64];
    {
        const float* wp = Wh + (size_t)(kh * 128) * G4 + colg;
#pragma unroll
        for (int jj = 0; jj < 64; jj++) {
            const float lo = __ldg(&wp[(size_t)(2 * jj) * G4]);
            const float hi = __ldg(&wp[(size_t)(2 * jj + 1) * G4]);
            w2[jj] = pk2(lo, hi);
        }
    }

    hs0[tid] = 0.f;
    hs1[tid] = 0.f;
    if (tid < 64) csm[tid >> 5][tid & 31] = 0.f;
    __syncthreads();

    // preload xg for t=0
    float xv0 = 0.f, xv1 = 0.f;
    if (kh == 0) {
        xv0 = __ldg(&g_xg[((size_t)(b0 * TT)) * G4 + colg]);
        xv1 = __ldg(&g_xg[((size_t)(b1 * TT)) * G4 + colg]);
    }

    for (int t = 0; t < TT; t++) {
        // partial dot over this lane's K-half, 2 batches, f32x2 packed along K
        const ulonglong2* h0v = (const ulonglong2*)&hs0[kh * 128];
        const ulonglong2* h1v = (const ulonglong2*)&hs1[kh * 128];
        unsigned long long a00 = 0ull, a01 = 0ull, a10 = 0ull, a11 = 0ull;
#pragma unroll
        for (int jj = 0; jj < 32; jj++) {
            const ulonglong2 h0 = h0v[jj];
            const ulonglong2 h1 = h1v[jj];
            a00 = ffma2(w2[2 * jj],     h0.x, a00);
            a01 = ffma2(w2[2 * jj + 1], h0.y, a01);
            a10 = ffma2(w2[2 * jj],     h1.x, a10);
            a11 = ffma2(w2[2 * jj + 1], h1.y, a11);
        }
        float s0, s1;
        {
            const float2 u0 = unpk2(a00), u1 = unpk2(a01);
            const float2 v0 = unpk2(a10), v1 = unpk2(a11);
            s0 = (u0.x + u0.y) + (u1.x + u1.y);
            s1 = (v0.x + v0.y) + (v1.x + v1.y);
        }
        s0 += __shfl_xor_sync(0xffffffffu, s0, 16);
        s1 += __shfl_xor_sync(0xffffffffu, s1, 16);
        if (kh == 0) {
            gsm0[q] = s0 + xv0;   // bias folded into xg
            gsm1[q] = s1 + xv1;
        }
        __syncthreads();   // gates visible; all FMA reads of hs0/hs1 done

        const int   s    = (t + 1) & 1;
        const float tagf = (float)(t + 1);

        // activation + state update (EXACT R4 structure) + tagged 8B store
        if (tid < 64) {
            const int bb = tid >> 5, ll = tid & 31;
            const float* gp = bb ? gsm1 : gsm0;
            const float gi = gp[ll];
            const float gf = gp[32 + ll];
            const float gg = gp[64 + ll];
            const float go = gp[96 + ll];
            const float cprev = csm[bb][ll];
            const float si = 1.f / (1.f + __expf(-gi));
            const float sf = 1.f / (1.f + __expf(-gf));
            const float so = 1.f / (1.f + __expf(-go));
            const float tg = 2.f / (1.f + __expf(-2.f * gg)) - 1.f;
            const float cn = sf * cprev + si * tg;
            const float tc = 2.f / (1.f + __expf(-2.f * cn)) - 1.f;
            const float hn = so * tc;
            csm[bb][ll] = cn;
            const int bg   = bb ? b1 : b0;
            const int hidx = j * 32 + ll;
            if (t + 1 < TT)
                st_rlx64(&g_hx[s][grp][hidx][bb], pk2(hn, tagf));
            g_hseq[((size_t)(bg * TT + t)) * HH + hidx] = hn;
        }
        // NO barrier here: warps 2-7 start polling while warps 0-1 finish

        if (t + 1 < TT) {
            // prefetch next xg (in flight during the poll)
            if (kh == 0) {
                xv0 = __ldg(&g_xg[((size_t)(b0 * TT + (t + 1))) * G4 + colg]);
                xv1 = __ldg(&g_xg[((size_t)(b1 * TT + (t + 1))) * G4 + colg]);
            }
            // each thread polls its OWN two tagged words; hit == data
            const unsigned long long* src = &g_hx[s][grp][tid][0];
            float2 d0, d1;
            for (;;) {
                const unsigned long long v0 = ld_rlx64(src);
                const unsigned long long v1 = ld_rlx64(src + 1);
                d0 = unpk2(v0);
                d1 = unpk2(v1);
                if (d0.y >= tagf && d1.y >= tagf) break;
            }
            hs0[tid] = d0.x;
            hs1[tid] = d1.x;
            __syncthreads();
        }
    }
}

// ---------------- launch ----------------
extern "C" void kernel_launch(void* const* d_in, const int* in_sizes, int n_in,
                              void* d_out, int out_size)
{
    const float* x  = (const float*)d_in[0];   // [B,T,DIN]
    const float* Wx = (const float*)d_in[1];   // [DIN,4H]
    const float* Wh = (const float*)d_in[2];   // [H,4H]
    const float* b  = (const float*)d_in[3];   // [4H]
    const float* Wo = (const float*)d_in[4];   // [H,DOUT]
    const float* bo = (const float*)d_in[5];   // [DOUT]
    float* out = (float*)d_out;                // [B,T,DOUT]

    float *xg_ptr = nullptr, *hseq_ptr = nullptr;
    cudaGetSymbolAddress((void**)&xg_ptr, g_xg);
    cudaGetSymbolAddress((void**)&hseq_ptr, g_hseq);

    // reset exchange tags (graph replays reuse device state)
    init_kernel<<<64, 256>>>();

    // 1) xg = x @ Wx + b : [131072,256] @ [256,1024]
    {
        dim3 grid(G4 / 128, (BB * TT) / 128);   // (8, 1024)
        sgemm_bias_128<<<grid, 256>>>(x, Wx, b, xg_ptr, BB * TT, G4, DIN);
    }

    // 2) recurrence over 4096 steps (16 groups x 8 CTAs, all co-resident)
    lstm_rec<<<128, 256>>>(Wh);

    // 3) out = hseq @ Wo + bo : [131072,256] @ [256,256]
    {
        dim3 grid(256 / 128, (BB * TT) / 128);  // (2, 1024)
        sgemm_bias_128<<<grid, 256>>>(hseq_ptr, Wo, bo, out, BB * TT, 256, HH);
    }
}